// round 15
// baseline (speedup 1.0000x reference)
#include <cuda_runtime.h>
#include <cuda_fp16.h>
#include <math.h>
#include <stdint.h>

#define B_  8
#define S_  2048
#define D_  64
#define H_  4096

// Scratch (__device__ globals: the sanctioned alloc-free path)
__device__ float  g_scores[(size_t)B_ * S_ * S_];     // 128 MB (adjusted logits), fp32
__device__ __half g_h_h   [(size_t)B_ * S_ * H_];     // 128 MB  h (fp16); reused for attn fp16
__device__ __half g_w1t_h [(size_t)H_ * S_];          // 16 MB   W1^T fp16 [4096,2048]
__device__ __half g_w2t_h [(size_t)S_ * H_];          // 16 MB   W2^T fp16 [2048,4096]
__device__ __half g_kt_h  [(size_t)B_ * D_ * S_];     // 2 MB    K^T stacked fp16 [512,2048]
__device__ __half g_kw1t_h[(size_t)B_ * H_ * D_];     // 4 MB    (K^T W1 / 8)^T fp16 [b][4096][64]
__device__ __half g_q_h   [(size_t)B_ * S_ * D_];     // 2 MB    Q fp16
__device__ __half g_vt_h  [(size_t)B_ * D_ * S_];     // 2 MB    V^T fp16 [b][64][2048]

// ---------------------------------------------------------------------------
// helpers
// ---------------------------------------------------------------------------
__device__ __forceinline__ void cp16(uint32_t dst, const void* src) {
    asm volatile("cp.async.cg.shared.global [%0], [%1], 16;" :: "r"(dst), "l"(src) : "memory");
}
#define CP_COMMIT() asm volatile("cp.async.commit_group;" ::: "memory")
#define CP_WAIT1()  asm volatile("cp.async.wait_group 1;" ::: "memory")
#define CP_WAIT0()  asm volatile("cp.async.wait_group 0;" ::: "memory")

__device__ __forceinline__ uint32_t smem_u32(const void* p) {
    uint32_t a;
    asm("{ .reg .u64 t; cvta.to.shared.u64 t, %1; cvt.u32.u64 %0, t; }" : "=r"(a) : "l"(p));
    return a;
}

#define MMA_F16(c, a, b)                                                       \
    asm volatile(                                                              \
        "mma.sync.aligned.m16n8k16.row.col.f32.f16.f16.f32 "                   \
        "{%0,%1,%2,%3}, {%4,%5,%6,%7}, {%8,%9}, {%0,%1,%2,%3};"                \
        : "+f"((c)[0]), "+f"((c)[1]), "+f"((c)[2]), "+f"((c)[3])               \
        : "r"((a)[0]), "r"((a)[1]), "r"((a)[2]), "r"((a)[3]),                  \
          "r"((b)[0]), "r"((b)[1]))

#define LDSM4(r0, r1, r2, r3, addr)                                            \
    asm volatile("ldmatrix.sync.aligned.m8n8.x4.shared.b16 {%0,%1,%2,%3}, [%4];"\
        : "=r"(r0), "=r"(r1), "=r"(r2), "=r"(r3) : "r"(addr))

constexpr int BM = 128, BN = 128, BK = 32, ST = 3;
constexpr int AW = 20;                     // smem row stride in 32-bit words (16 + 4 pad)
constexpr int TILE_H_BYTES = 128 * AW * 4; // 10240 per 128-row operand
constexpr int STAGE_BYTES = 2 * TILE_H_BYTES;   // 20480
constexpr int GEMM_SMEM = ST * STAGE_BYTES;     // 61440

// ---------------------------------------------------------------------------
// fp16 mma.sync GEMM (128x128 tile):  C[z] = act(scale * (A[z] @ Bt[z]^T) + bias)
// 8 warps (2x4), warp tile 64x32, 2 CTAs/SM, ldmatrix fragments.
// OUT: 0 = fp32 row-major, 1 = fp16 row-major, 2 = fp16 transposed for kw1t.
// ---------------------------------------------------------------------------
__device__ __forceinline__ void load_stage(uint32_t sb, int s, const __half* gA,
                                           const __half* gB, int K, int k0, int tid) {
    const uint32_t aB = sb + s * STAGE_BYTES;
    const uint32_t bB = aB + TILE_H_BYTES;
    #pragma unroll
    for (int i = 0; i < 2; i++) {
        int t = i * 256 + tid;
        int r = t >> 2, c = t & 3;
        cp16(aB + (uint32_t)(r * AW + c * 4) * 4, gA + (size_t)r * K + k0 + c * 8);
    }
    #pragma unroll
    for (int i = 0; i < 2; i++) {
        int t = i * 256 + tid;
        int r = t >> 2, c = t & 3;
        cp16(bB + (uint32_t)(r * AW + c * 4) * 4, gB + (size_t)r * K + k0 + c * 8);
    }
    CP_COMMIT();
}

template <int OUT, bool RELU, bool BIAS>
__global__ __launch_bounds__(256, 2)
void mma_gemm_h(const __half* __restrict__ A, const __half* __restrict__ Bt,
                const float* __restrict__ bias, void* __restrict__ Cv,
                int M, int N, int K, float scale,
                size_t aStride, size_t bStride, size_t cStride) {
    extern __shared__ char smem[];
    const uint32_t sb = smem_u32(smem);
    const int tid = threadIdx.x;
    const int w = tid >> 5, L = tid & 31;
    const int wm = (w >> 2) * 64;
    const int wn = (w & 3) * 32;
    const int q = L & 3, r4 = L >> 2;

    const int m0 = blockIdx.y * BM, n0 = blockIdx.x * BN;
    A  += (size_t)blockIdx.z * aStride;
    Bt += (size_t)blockIdx.z * bStride;
    const __half* gA = A + (size_t)m0 * K;
    const __half* gB = Bt + (size_t)n0 * K;
    const int NC = K / BK;

    const int aRowL  = wm + (L & 7) + ((L >> 3) & 1) * 8;
    const int aWordL = ((L >> 4) & 1) * 4;
    const int bRowL  = wn + ((L >> 4) & 1) * 8 + (L & 7);
    const int bWordL = ((L >> 3) & 1) * 4;

    float c[4][4][4] = {};

    load_stage(sb, 0, gA, gB, K, 0, tid);
    load_stage(sb, 1, gA, gB, K, BK, tid);

    for (int cc = 0; cc < NC; cc++) {
        if (cc == NC - 1) { CP_WAIT0(); } else { CP_WAIT1(); }
        __syncthreads();
        if (cc + 2 < NC)
            load_stage(sb, (cc + 2) % ST, gA, gB, K, (cc + 2) * BK, tid);

        const int s = cc % ST;
        const uint32_t aBase = sb + s * STAGE_BYTES;
        const uint32_t bBase = aBase + TILE_H_BYTES;

        #pragma unroll
        for (int ks = 0; ks < 2; ks++) {
            uint32_t af[4][4], bf[4][2];
            #pragma unroll
            for (int mt = 0; mt < 4; mt++) {
                const uint32_t addr =
                    aBase + (uint32_t)((aRowL + mt * 16) * AW + aWordL + ks * 8) * 4;
                LDSM4(af[mt][0], af[mt][1], af[mt][2], af[mt][3], addr);
            }
            #pragma unroll
            for (int p = 0; p < 2; p++) {
                const uint32_t addr =
                    bBase + (uint32_t)((bRowL + p * 16) * AW + bWordL + ks * 8) * 4;
                LDSM4(bf[p * 2][0], bf[p * 2][1], bf[p * 2 + 1][0], bf[p * 2 + 1][1], addr);
            }
            #pragma unroll
            for (int mt = 0; mt < 4; mt++)
                #pragma unroll
                for (int nt = 0; nt < 4; nt++)
                    MMA_F16(c[mt][nt], af[mt], bf[nt]);
        }
    }

    #pragma unroll
    for (int mt = 0; mt < 4; mt++) {
        #pragma unroll
        for (int nt = 0; nt < 4; nt++) {
            const int col = n0 + wn + nt * 8 + q * 2;
            float2 bv = BIAS ? *(const float2*)(bias + col) : make_float2(0.f, 0.f);
            #pragma unroll
            for (int hh = 0; hh < 2; hh++) {
                const int row = m0 + wm + mt * 16 + r4 + hh * 8;
                float ox = c[mt][nt][hh * 2 + 0] * scale + bv.x;
                float oy = c[mt][nt][hh * 2 + 1] * scale + bv.y;
                if (RELU) { ox = fmaxf(ox, 0.f); oy = fmaxf(oy, 0.f); }
                if (OUT == 0) {
                    float* C = (float*)Cv + (size_t)blockIdx.z * cStride;
                    *(float2*)(C + (size_t)row * N + col) = make_float2(ox, oy);
                } else if (OUT == 1) {
                    __half* C = (__half*)Cv + (size_t)blockIdx.z * cStride;
                    *(__half2*)(C + (size_t)row * N + col) =
                        __floats2half2_rn(ox, oy);
                } else {
                    __half* C = (__half*)Cv;
                    const size_t base = ((size_t)(row >> 6) * N) * 64 + (row & 63);
                    C[base + (size_t)col * 64]       = __float2half_rn(ox);
                    C[base + (size_t)(col + 1) * 64] = __float2half_rn(oy);
                }
            }
        }
    }
}

// ---------------------------------------------------------------------------
// BIG-TILE fp16 GEMM for GEMM3: C[z] = A[z] @ Bt^T + bias  (fp32 out)
// CTA tile 256x128, BK=32, 3-stage, 8 warps as 4(m)x2(n), warp tile 64x64.
// 1 CTA/SM (high reg count); halves B-side L2 traffic vs 128x128.
// ---------------------------------------------------------------------------
constexpr int BG_M = 256;
constexpr int BG_ATILE = 256 * AW * 4;                   // 20480
constexpr int BG_STAGE = BG_ATILE + TILE_H_BYTES;        // 30720
constexpr int BG_SMEM = ST * BG_STAGE;                   // 92160

__global__ __launch_bounds__(256, 1)
void mma_gemm_big(const __half* __restrict__ A, const __half* __restrict__ Bt,
                  const float* __restrict__ bias, float* __restrict__ C,
                  int M, int N, int K, size_t aStride, size_t cStride) {
    extern __shared__ char smem[];
    const uint32_t sb = smem_u32(smem);
    const int tid = threadIdx.x;
    const int w = tid >> 5, L = tid & 31;
    const int wm = (w >> 1) * 64;          // 4 m-groups of 64
    const int wn = (w & 1) * 64;           // 2 n-groups of 64
    const int q = L & 3, r4 = L >> 2;

    const int m0 = blockIdx.y * BG_M, n0 = blockIdx.x * BN;
    A += (size_t)blockIdx.z * aStride;
    C += (size_t)blockIdx.z * cStride;
    const __half* gA = A + (size_t)m0 * K;
    const __half* gB = Bt + (size_t)n0 * K;
    const int NC = K / BK;

    const int aRowL  = wm + (L & 7) + ((L >> 3) & 1) * 8;
    const int aWordL = ((L >> 4) & 1) * 4;
    const int bRowL  = wn + ((L >> 4) & 1) * 8 + (L & 7);
    const int bWordL = ((L >> 3) & 1) * 4;

    float c[4][8][4] = {};   // [mt][nt][frag] — 128 regs

    auto load_big = [&](int s, int k0) {
        const uint32_t aB = sb + s * BG_STAGE;
        const uint32_t bB = aB + BG_ATILE;
        #pragma unroll
        for (int i = 0; i < 4; i++) {               // A: 256 rows x 4 chunks
            int t = i * 256 + tid;
            int r = t >> 2, cch = t & 3;
            cp16(aB + (uint32_t)(r * AW + cch * 4) * 4, gA + (size_t)r * K + k0 + cch * 8);
        }
        #pragma unroll
        for (int i = 0; i < 2; i++) {               // B: 128 rows x 4 chunks
            int t = i * 256 + tid;
            int r = t >> 2, cch = t & 3;
            cp16(bB + (uint32_t)(r * AW + cch * 4) * 4, gB + (size_t)r * K + k0 + cch * 8);
        }
        CP_COMMIT();
    };

    load_big(0, 0);
    load_big(1, BK);

    for (int cc = 0; cc < NC; cc++) {
        if (cc == NC - 1) { CP_WAIT0(); } else { CP_WAIT1(); }
        __syncthreads();
        if (cc + 2 < NC) load_big((cc + 2) % ST, (cc + 2) * BK);

        const int s = cc % ST;
        const uint32_t aBase = sb + s * BG_STAGE;
        const uint32_t bBase = aBase + BG_ATILE;

        #pragma unroll
        for (int ks = 0; ks < 2; ks++) {
            uint32_t af[4][4], bf[8][2];
            #pragma unroll
            for (int mt = 0; mt < 4; mt++) {
                const uint32_t addr =
                    aBase + (uint32_t)((aRowL + mt * 16) * AW + aWordL + ks * 8) * 4;
                LDSM4(af[mt][0], af[mt][1], af[mt][2], af[mt][3], addr);
            }
            #pragma unroll
            for (int p = 0; p < 4; p++) {
                const uint32_t addr =
                    bBase + (uint32_t)((bRowL + p * 16) * AW + bWordL + ks * 8) * 4;
                LDSM4(bf[p * 2][0], bf[p * 2][1], bf[p * 2 + 1][0], bf[p * 2 + 1][1], addr);
            }
            #pragma unroll
            for (int mt = 0; mt < 4; mt++)
                #pragma unroll
                for (int nt = 0; nt < 8; nt++)
                    MMA_F16(c[mt][nt], af[mt], bf[nt]);
        }
    }

    #pragma unroll
    for (int mt = 0; mt < 4; mt++) {
        #pragma unroll
        for (int nt = 0; nt < 8; nt++) {
            const int col = n0 + wn + nt * 8 + q * 2;
            const float2 bv = *(const float2*)(bias + col);
            #pragma unroll
            for (int hh = 0; hh < 2; hh++) {
                const int row = m0 + wm + mt * 16 + r4 + hh * 8;
                *(float2*)(C + (size_t)row * N + col) =
                    make_float2(c[mt][nt][hh * 2 + 0] + bv.x,
                                c[mt][nt][hh * 2 + 1] + bv.y);
            }
        }
    }
}

// ---------------------------------------------------------------------------
// AV tensor-core GEMM: out[z] = attn[z] @ Vt[z]^T
// CTA tile 128x64, BK=32, 3-stage, 8 warps as 4(m)x2(n), warp tile 32x32.
// ---------------------------------------------------------------------------
constexpr int AV_BTILE = 64 * AW * 4;                    // 5120
constexpr int AV_STAGE = TILE_H_BYTES + AV_BTILE;        // 15360
constexpr int AV_SMEM = ST * AV_STAGE;                   // 46080

__global__ __launch_bounds__(256, 2)
void av_mma(const __half* __restrict__ attn, const __half* __restrict__ Vt,
            float* __restrict__ out) {
    extern __shared__ char smem[];
    const uint32_t sb = smem_u32(smem);
    const int tid = threadIdx.x;
    const int w = tid >> 5, L = tid & 31;
    const int wm = (w >> 1) * 32;
    const int wn = (w & 1) * 32;
    const int q = L & 3, r4 = L >> 2;
    const int K = S_;

    const int m0 = blockIdx.y * BM;
    const int z = blockIdx.z;
    const __half* gA = attn + (size_t)z * S_ * S_ + (size_t)m0 * K;
    const __half* gB = Vt + (size_t)z * D_ * S_;
    const int NC = K / BK;

    const int aRowL  = wm + (L & 7) + ((L >> 3) & 1) * 8;
    const int aWordL = ((L >> 4) & 1) * 4;
    const int bRowL  = wn + ((L >> 4) & 1) * 8 + (L & 7);
    const int bWordL = ((L >> 3) & 1) * 4;

    float c[2][4][4] = {};

    auto load_av = [&](int s, int k0) {
        const uint32_t aB = sb + s * AV_STAGE;
        const uint32_t bB = aB + TILE_H_BYTES;
        #pragma unroll
        for (int i = 0; i < 2; i++) {
            int t = i * 256 + tid;
            int r = t >> 2, cch = t & 3;
            cp16(aB + (uint32_t)(r * AW + cch * 4) * 4, gA + (size_t)r * K + k0 + cch * 8);
        }
        {
            int r = tid >> 2, cch = tid & 3;
            cp16(bB + (uint32_t)(r * AW + cch * 4) * 4, gB + (size_t)r * K + k0 + cch * 8);
        }
        CP_COMMIT();
    };

    load_av(0, 0);
    load_av(1, BK);

    for (int cc = 0; cc < NC; cc++) {
        if (cc == NC - 1) { CP_WAIT0(); } else { CP_WAIT1(); }
        __syncthreads();
        if (cc + 2 < NC) load_av((cc + 2) % ST, (cc + 2) * BK);

        const int s = cc % ST;
        const uint32_t aBase = sb + s * AV_STAGE;
        const uint32_t bBase = aBase + TILE_H_BYTES;

        #pragma unroll
        for (int ks = 0; ks < 2; ks++) {
            uint32_t af[2][4], bf[4][2];
            #pragma unroll
            for (int mt = 0; mt < 2; mt++) {
                const uint32_t addr =
                    aBase + (uint32_t)((aRowL + mt * 16) * AW + aWordL + ks * 8) * 4;
                LDSM4(af[mt][0], af[mt][1], af[mt][2], af[mt][3], addr);
            }
            #pragma unroll
            for (int p = 0; p < 2; p++) {
                const uint32_t addr =
                    bBase + (uint32_t)((bRowL + p * 16) * AW + bWordL + ks * 8) * 4;
                LDSM4(bf[p * 2][0], bf[p * 2][1], bf[p * 2 + 1][0], bf[p * 2 + 1][1], addr);
            }
            #pragma unroll
            for (int mt = 0; mt < 2; mt++)
                #pragma unroll
                for (int nt = 0; nt < 4; nt++)
                    MMA_F16(c[mt][nt], af[mt], bf[nt]);
        }
    }

    #pragma unroll
    for (int mt = 0; mt < 2; mt++) {
        #pragma unroll
        for (int nt = 0; nt < 4; nt++) {
            const int col = wn + nt * 8 + q * 2;
            #pragma unroll
            for (int hh = 0; hh < 2; hh++) {
                const int row = m0 + wm + mt * 16 + r4 + hh * 8;
                *(float2*)(out + ((size_t)z * S_ + row) * D_ + col) =
                    make_float2(c[mt][nt][hh * 2 + 0], c[mt][nt][hh * 2 + 1]);
            }
        }
    }
}

// ---------------------------------------------------------------------------
// transpose_h: out[c][r] = fp16(in[r][c]) per batch; in [R,C] fp32.
// ---------------------------------------------------------------------------
__global__ __launch_bounds__(256)
void transpose_h(const float* __restrict__ in, __half* __restrict__ out,
                 int R, int C, size_t inStride, size_t outStride) {
    __shared__ float t[32][33];
    const int z = blockIdx.z;
    const int c0 = blockIdx.x * 32, r0 = blockIdx.y * 32;
    const float* ib = in + (size_t)z * inStride;
    #pragma unroll
    for (int i = 0; i < 4; i++)
        t[threadIdx.y + i * 8][threadIdx.x] =
            ib[(size_t)(r0 + threadIdx.y + i * 8) * C + c0 + threadIdx.x];
    __syncthreads();
    __half* ob = out + (size_t)z * outStride;
    #pragma unroll
    for (int i = 0; i < 4; i++)
        ob[(size_t)(c0 + threadIdx.y + i * 8) * R + r0 + threadIdx.x] =
            __float2half_rn(t[threadIdx.x][threadIdx.y + i * 8]);
}

// ---------------------------------------------------------------------------
// conv_h: fp32 -> fp16 elementwise (vectorized 4-wide)
// ---------------------------------------------------------------------------
__global__ __launch_bounds__(256)
void conv_h(const float* __restrict__ in, __half* __restrict__ out, int n4) {
    int i = blockIdx.x * 256 + threadIdx.x;
    if (i < n4) {
        float4 v = ((const float4*)in)[i];
        __half2 a = __floats2half2_rn(v.x, v.y);
        __half2 b = __floats2half2_rn(v.z, v.w);
        *(uint32_t*)&((__half*)out)[i * 4]     = *(uint32_t*)&a;
        *(uint32_t*)&((__half*)out)[i * 4 + 2] = *(uint32_t*)&b;
    }
}

// ---------------------------------------------------------------------------
// Row softmax over S_=2048: read fp32 logits, write fp16 attn.
// ---------------------------------------------------------------------------
__global__ __launch_bounds__(256)
void softmax_h_kernel(const float* __restrict__ X, __half* __restrict__ Y) {
    __shared__ float red[8];
    const float* x = X + (size_t)blockIdx.x * S_;
    __half* y = Y + (size_t)blockIdx.x * S_;
    const int tid = threadIdx.x;
    const int wid = tid >> 5, lane = tid & 31;

    float4 v0 = ((const float4*)x)[tid];
    float4 v1 = ((const float4*)x)[tid + 256];

    float m = fmaxf(fmaxf(fmaxf(v0.x, v0.y), fmaxf(v0.z, v0.w)),
                    fmaxf(fmaxf(v1.x, v1.y), fmaxf(v1.z, v1.w)));
    #pragma unroll
    for (int o = 16; o > 0; o >>= 1) m = fmaxf(m, __shfl_xor_sync(0xffffffffu, m, o));
    if (lane == 0) red[wid] = m;
    __syncthreads();
    if (tid < 32) {
        float t = (tid < 8) ? red[tid] : -INFINITY;
        #pragma unroll
        for (int o = 4; o > 0; o >>= 1) t = fmaxf(t, __shfl_xor_sync(0xffffffffu, t, o));
        if (tid == 0) red[0] = t;
    }
    __syncthreads();
    m = red[0];
    __syncthreads();

    v0.x = __expf(v0.x - m); v0.y = __expf(v0.y - m);
    v0.z = __expf(v0.z - m); v0.w = __expf(v0.w - m);
    v1.x = __expf(v1.x - m); v1.y = __expf(v1.y - m);
    v1.z = __expf(v1.z - m); v1.w = __expf(v1.w - m);
    float s = (v0.x + v0.y + v0.z + v0.w) + (v1.x + v1.y + v1.z + v1.w);
    #pragma unroll
    for (int o = 16; o > 0; o >>= 1) s += __shfl_xor_sync(0xffffffffu, s, o);
    if (lane == 0) red[wid] = s;
    __syncthreads();
    if (tid < 32) {
        float t = (tid < 8) ? red[tid] : 0.f;
        #pragma unroll
        for (int o = 4; o > 0; o >>= 1) t += __shfl_xor_sync(0xffffffffu, t, o);
        if (tid == 0) red[0] = t;
    }
    __syncthreads();
    const float inv = 1.0f / red[0];

    __half2 h0 = __floats2half2_rn(v0.x * inv, v0.y * inv);
    __half2 h1 = __floats2half2_rn(v0.z * inv, v0.w * inv);
    __half2 h2 = __floats2half2_rn(v1.x * inv, v1.y * inv);
    __half2 h3 = __floats2half2_rn(v1.z * inv, v1.w * inv);
    ((__half2*)y)[tid * 2]             = h0;
    ((__half2*)y)[tid * 2 + 1]         = h1;
    ((__half2*)y)[(tid + 256) * 2]     = h2;
    ((__half2*)y)[(tid + 256) * 2 + 1] = h3;
}

// ---------------------------------------------------------------------------
// Launch
// ---------------------------------------------------------------------------
extern "C" void kernel_launch(void* const* d_in, const int* in_sizes, int n_in,
                              void* d_out, int out_size) {
    const float* Q  = (const float*)d_in[0];
    const float* K  = (const float*)d_in[1];
    const float* V  = (const float*)d_in[2];
    const float* W1 = (const float*)d_in[3];
    const float* b1 = (const float*)d_in[4];
    const float* W2 = (const float*)d_in[5];
    const float* b2 = (const float*)d_in[6];
    float* out = (float*)d_out;

    float *scores;
    __half *hh, *w1t, *w2t, *kt, *kw1t, *qh, *vt;
    cudaGetSymbolAddress((void**)&scores, g_scores);
    cudaGetSymbolAddress((void**)&hh, g_h_h);
    cudaGetSymbolAddress((void**)&w1t, g_w1t_h);
    cudaGetSymbolAddress((void**)&w2t, g_w2t_h);
    cudaGetSymbolAddress((void**)&kt, g_kt_h);
    cudaGetSymbolAddress((void**)&kw1t, g_kw1t_h);
    cudaGetSymbolAddress((void**)&qh, g_q_h);
    cudaGetSymbolAddress((void**)&vt, g_vt_h);

    cudaFuncSetAttribute(mma_gemm_h<2, false, false>,
                         cudaFuncAttributeMaxDynamicSharedMemorySize, GEMM_SMEM);
    cudaFuncSetAttribute(mma_gemm_h<1, true, true>,
                         cudaFuncAttributeMaxDynamicSharedMemorySize, GEMM_SMEM);
    cudaFuncSetAttribute(mma_gemm_big,
                         cudaFuncAttributeMaxDynamicSharedMemorySize, BG_SMEM);
    cudaFuncSetAttribute(av_mma,
                         cudaFuncAttributeMaxDynamicSharedMemorySize, AV_SMEM);

    // 0) fp16 operands
    transpose_h<<<dim3(H_ / 32, S_ / 32, 1), dim3(32, 8)>>>(W1, w1t, S_, H_, 0, 0);
    transpose_h<<<dim3(S_ / 32, H_ / 32, 1), dim3(32, 8)>>>(W2, w2t, H_, S_, 0, 0);
    transpose_h<<<dim3(D_ / 32, S_ / 32, B_), dim3(32, 8)>>>(
        K, kt, S_, D_, (size_t)S_ * D_, (size_t)D_ * S_);
    transpose_h<<<dim3(D_ / 32, S_ / 32, B_), dim3(32, 8)>>>(
        V, vt, S_, D_, (size_t)S_ * D_, (size_t)D_ * S_);
    conv_h<<<(B_ * S_ * D_ / 4 + 255) / 256, 256>>>(Q, qh, B_ * S_ * D_ / 4);

    // 1) kw1t = fp16((K^T @ W1)/8), stored transposed per batch [4096,64]
    mma_gemm_h<2, false, false><<<dim3(H_ / BN, (B_ * D_) / BM, 1), 256, GEMM_SMEM>>>(
        kt, w1t, nullptr, kw1t, B_ * D_, H_, S_, 0.125f, 0, 0, 0);

    // 2) h = fp16(relu(Q @ KW1 + b1)) per batch; Bt = kw1t [4096,64]
    mma_gemm_h<1, true, true><<<dim3(H_ / BN, S_ / BM, B_), 256, GEMM_SMEM>>>(
        qh, kw1t, b1, hh, S_, H_, D_, 1.0f,
        (size_t)S_ * D_, (size_t)H_ * D_, (size_t)S_ * H_);

    // 3) adjusted = h @ W2 + b2 -> scores (fp32)  [BIG-TILE 256x128 kernel]
    mma_gemm_big<<<dim3(S_ / BN, S_ / BG_M, B_), 256, BG_SMEM>>>(
        hh, w2t, b2, scores, S_, S_, H_,
        (size_t)S_ * H_, (size_t)S_ * S_);

    // 4) softmax rows: fp32 logits -> fp16 attn (into hh, free after GEMM3)
    softmax_h_kernel<<<B_ * S_, 256>>>(scores, hh);

    // 5) out = attn @ V  (tensor cores)
    av_mma<<<dim3(1, S_ / BM, B_), 256, AV_SMEM>>>(hh, vt, out);
}